// round 5
// baseline (speedup 1.0000x reference)
#include <cuda_runtime.h>
#include <cuda_bf16.h>
#include <cstdint>
#include <cstddef>

// Problem dims: B=32, S=1024, D=256, L=4, O=64, V=5. Two encodes -> 64 seqs.
#define NROWS 65536          // 2 * 32 * 1024

// ---------------- device scratch (static; no runtime allocation) ----------------
__device__ float g_h  [(size_t)NROWS * 256];   // residual stream
__device__ float g_hn [(size_t)NROWS * 256];   // LN out, later reused as gated "c"
__device__ float g_f  [(size_t)NROWS * 256];   // forward GRU out
__device__ float g_r  [(size_t)NROWS * 256];   // reverse GRU out (natural time order)
__device__ float g_xif[(size_t)NROWS * 768];   // xi forward
__device__ float g_xir[(size_t)NROWS * 768];   // xi reverse
__device__ float g_pool[32 * 256];
__device__ float g_hbuf[8 * 2 * 16 * 256];     // [group][parity][row16][unit256]
__device__ unsigned g_cnt[8];

// ---------------- helpers ----------------
__device__ __forceinline__ unsigned f2tfu(float x) {
    unsigned u; asm("cvt.rna.tf32.f32 %0, %1;" : "=r"(u) : "f"(x)); return u;
}
__device__ __forceinline__ float f2tff(float x) {
    return __uint_as_float(f2tfu(x));
}
__device__ __forceinline__ void mma_tf32(float* c, const unsigned* a, unsigned b0, unsigned b1) {
    asm volatile(
        "mma.sync.aligned.m16n8k8.row.col.f32.tf32.tf32.f32 "
        "{%0,%1,%2,%3}, {%4,%5,%6,%7}, {%8,%9}, {%0,%1,%2,%3};\n"
        : "+f"(c[0]), "+f"(c[1]), "+f"(c[2]), "+f"(c[3])
        : "r"(a[0]), "r"(a[1]), "r"(a[2]), "r"(a[3]), "r"(b0), "r"(b1));
}
__device__ __forceinline__ unsigned ld_acq(const unsigned* p) {
    unsigned v; asm volatile("ld.global.acquire.gpu.u32 %0, [%1];" : "=r"(v) : "l"(p)); return v;
}
__device__ __forceinline__ float sigf(float x) { return 1.0f / (1.0f + expf(-x)); }

// ---------------- embedding (both encodes) ----------------
// row = e*32768 + b*1024 + s ; e=1 is reverse-complement sequence
__global__ void embed_kernel(const int* __restrict__ tok, const float* __restrict__ emb,
                             const float* __restrict__ pos) {
    int bid = blockIdx.x;
    int d = threadIdx.x;
    int e = bid >> 15, rem = bid & 32767, b = rem >> 10, s = rem & 1023;
    int t;
    if (e == 0) t = tok[b * 1024 + s];
    else { int t0 = tok[b * 1024 + (1023 - s)]; t = (t0 < 4) ? (3 - t0) : 4; }
    g_h[(size_t)bid * 256 + d] = emb[t * 256 + d] + pos[s * 256 + d];
}

// ---------------- layernorm over D=256 (one warp per row, 8 rows per CTA) ----------------
__global__ void ln_kernel(const float* __restrict__ X, const float* __restrict__ gw,
                          const float* __restrict__ gb, float* __restrict__ Y) {
    int warp = threadIdx.x >> 5, lane = threadIdx.x & 31;
    int row = blockIdx.x * 8 + warp;
    const float* x = X + (size_t)row * 256;
    float v[8];
#pragma unroll
    for (int i = 0; i < 8; i++) v[i] = x[lane + i * 32];
    float s = 0.f;
#pragma unroll
    for (int i = 0; i < 8; i++) s += v[i];
#pragma unroll
    for (int o = 16; o > 0; o >>= 1) s += __shfl_xor_sync(0xffffffffu, s, o);
    float m = s * (1.0f / 256.0f);
    float q = 0.f;
#pragma unroll
    for (int i = 0; i < 8; i++) { float d = v[i] - m; q += d * d; }
#pragma unroll
    for (int o = 16; o > 0; o >>= 1) q += __shfl_xor_sync(0xffffffffu, q, o);
    float rs = rsqrtf(q * (1.0f / 256.0f) + 1e-5f);
    float* y = Y + (size_t)row * 256;
#pragma unroll
    for (int i = 0; i < 8; i++) {
        int d = lane + i * 32;
        y[d] = (v[i] - m) * rs * gw[d] + gb[d];
    }
}

// ---------------- tf32 GEMM: out = act(A @ W^T + bias) ----------------
// MODE 0: xi   (K=256, N=768, plain + bias)
// MODE 1: gate (K=512: k<256 from A=f, k>=256 from A2=r; N=256; out = g*f+(1-g)*r)
// MODE 2: oproj(K=256, N=256; out += val + bias  (residual))
template <int MODE>
__global__ __launch_bounds__(256)
void gemm_kernel(const float* __restrict__ A, const float* __restrict__ A2,
                 const float* __restrict__ W, const float* __restrict__ bias,
                 float* __restrict__ out) {
    __shared__ float sA[128 * 36];
    __shared__ float sB[64 * 36];
    const int KT  = (MODE == 1) ? 512 : 256;
    const int WLD = (MODE == 1) ? 512 : 256;
    int tid = threadIdx.x, lane = tid & 31, warp = tid >> 5;
    int wm = warp >> 1, wn = warp & 1;
    int rowBase = blockIdx.y * 128;
    int colBase = blockIdx.x * 64;
    int g = lane >> 2, q = lane & 3;

    float acc[2][4][4];
#pragma unroll
    for (int a = 0; a < 2; a++)
#pragma unroll
        for (int b = 0; b < 4; b++)
#pragma unroll
            for (int c = 0; c < 4; c++) acc[a][b][c] = 0.f;

    for (int k0 = 0; k0 < KT; k0 += 32) {
        const float* Asrc = (MODE == 1 && k0 >= 256) ? A2 : A;
        int kA = (MODE == 1) ? (k0 & 255) : k0;
#pragma unroll
        for (int i = 0; i < 4; i++) {
            int flat = tid + i * 256;          // 1024 float4 total
            int r = flat >> 3, c4 = flat & 7;
            float4 v = *(const float4*)&Asrc[(size_t)(rowBase + r) * 256 + kA + c4 * 4];
            float* d = &sA[r * 36 + c4 * 4];
            d[0] = f2tff(v.x); d[1] = f2tff(v.y); d[2] = f2tff(v.z); d[3] = f2tff(v.w);
        }
#pragma unroll
        for (int i = 0; i < 2; i++) {
            int flat = tid + i * 256;          // 512 float4 total
            int r = flat >> 3, c4 = flat & 7;
            float4 v = *(const float4*)&W[(size_t)(colBase + r) * WLD + k0 + c4 * 4];
            float* d = &sB[r * 36 + c4 * 4];
            d[0] = f2tff(v.x); d[1] = f2tff(v.y); d[2] = f2tff(v.z); d[3] = f2tff(v.w);
        }
        __syncthreads();
#pragma unroll
        for (int kk = 0; kk < 4; kk++) {
            int ko = kk * 8;
            unsigned a[2][4];
#pragma unroll
            for (int mt = 0; mt < 2; mt++) {
                int rb = wm * 32 + mt * 16;
                a[mt][0] = __float_as_uint(sA[(rb + g) * 36 + ko + q]);
                a[mt][1] = __float_as_uint(sA[(rb + g + 8) * 36 + ko + q]);
                a[mt][2] = __float_as_uint(sA[(rb + g) * 36 + ko + q + 4]);
                a[mt][3] = __float_as_uint(sA[(rb + g + 8) * 36 + ko + q + 4]);
            }
#pragma unroll
            for (int nt = 0; nt < 4; nt++) {
                int nb = wn * 32 + nt * 8;
                unsigned b0 = __float_as_uint(sB[(nb + g) * 36 + ko + q]);
                unsigned b1 = __float_as_uint(sB[(nb + g) * 36 + ko + q + 4]);
                mma_tf32(acc[0][nt], a[0], b0, b1);
                mma_tf32(acc[1][nt], a[1], b0, b1);
            }
        }
        __syncthreads();
    }
    // epilogue
#pragma unroll
    for (int mt = 0; mt < 2; mt++)
#pragma unroll
        for (int nt = 0; nt < 4; nt++)
#pragma unroll
            for (int i = 0; i < 4; i++) {
                int row = rowBase + wm * 32 + mt * 16 + g + ((i & 2) ? 8 : 0);
                int coln = colBase + wn * 32 + nt * 8 + 2 * q + (i & 1);
                float val = acc[mt][nt][i] + bias[coln];
                if (MODE == 0) {
                    out[(size_t)row * 768 + coln] = val;
                } else if (MODE == 1) {
                    float gg = sigf(val);
                    float fv = A [(size_t)row * 256 + coln];
                    float rv = A2[(size_t)row * 256 + coln];
                    out[(size_t)row * 256 + coln] = gg * fv + (1.0f - gg) * rv;
                } else {
                    out[(size_t)row * 256 + coln] += val;
                }
            }
}

// ---------------- persistent bidirectional GRU scan ----------------
// 128 CTAs: dir(2) x batch-slice(4, 16 rows) x unit-slice(16, 16 hidden units).
// Group = dir*4+bs (16 CTAs) exchanges h via double-buffered g_hbuf + counter barrier.
#define RNN_SMEM ((48*260 + 16*260 + 4*16*48 + 48) * 4)

__global__ __launch_bounds__(128)
void rnn_kernel(const float* __restrict__ whhF, const float* __restrict__ whhR,
                const float* __restrict__ bhhF, const float* __restrict__ bhhR) {
    extern __shared__ float sm[];
    float* sW   = sm;                 // 48 x 260 (tf32)
    float* sH   = sW + 48 * 260;      // 16 x 260 (full fp32 h tile)
    float* sRed = sH + 16 * 260;      // 4 warps x 16 x 48 partials
    float* sBhh = sRed + 4 * 16 * 48; // 48

    int cta = blockIdx.x;
    int dir = cta >> 6, rem = cta & 63, bs = rem >> 4, u = rem & 15;
    int group = dir * 4 + bs;
    const float* W    = dir ? whhR : whhF;
    const float* bhh  = dir ? bhhR : bhhF;
    const float* xi   = dir ? g_xir : g_xif;
    float*       outp = dir ? g_r   : g_f;
    float*    buf = g_hbuf + (size_t)group * 8192;   // 2 x 16 x 256
    unsigned* cnt = &g_cnt[group];

    int tid = threadIdx.x, lane = tid & 31, warp = tid >> 5;
    int g = lane >> 2, q = lane & 3;

    // load weight slice (gate rows: r,z,n for units u*16..u*16+15) -> tf32 in SMEM
    for (int idx = tid; idx < 48 * 256; idx += 128) {
        int rI = idx >> 8, k = idx & 255;
        int grow = (rI >> 4) * 256 + u * 16 + (rI & 15);
        sW[rI * 260 + k] = f2tff(W[(size_t)grow * 256 + k]);
    }
    if (tid < 48) {
        int grow = (tid >> 4) * 256 + u * 16 + (tid & 15);
        sBhh[tid] = bhh[grow];
    }
    // zero my block of h buffer parity 0
    for (int idx = tid; idx < 256; idx += 128) {
        int lr = idx >> 4, c = idx & 15;
        buf[lr * 256 + u * 16 + c] = 0.f;
    }
    __syncthreads();
    if (tid == 0) { __threadfence(); atomicAdd(cnt, 1u); }
    unsigned target = 16u;
    if (tid == 0) { while (ld_acq(cnt) < target) {} }
    __syncthreads();

    for (int t = 0; t < 1024; t++) {
        int par = t & 1;
        // stage full h tile (16 rows x 256) for my batch slice
        for (int idx = tid; idx < 1024; idx += 128) {
            int lr = idx >> 6, c4 = idx & 63;
            float4 v = *(const float4*)&buf[par * 4096 + lr * 256 + c4 * 4];
            float* d = &sH[lr * 260 + c4 * 4];
            d[0] = v.x; d[1] = v.y; d[2] = v.z; d[3] = v.w;
        }
        __syncthreads();

        // MMA: 16x48 = h(16x256) @ Wslice^T(48x256), k split across 4 warps
        float c[6][4];
#pragma unroll
        for (int j = 0; j < 6; j++)
#pragma unroll
            for (int i = 0; i < 4; i++) c[j][i] = 0.f;
        int kbase = warp * 64;
#pragma unroll
        for (int ks = 0; ks < 8; ks++) {
            int k0 = kbase + ks * 8;
            unsigned a[4];
            a[0] = f2tfu(sH[g * 260 + k0 + q]);
            a[1] = f2tfu(sH[(g + 8) * 260 + k0 + q]);
            a[2] = f2tfu(sH[g * 260 + k0 + q + 4]);
            a[3] = f2tfu(sH[(g + 8) * 260 + k0 + q + 4]);
#pragma unroll
            for (int j = 0; j < 6; j++) {
                unsigned b0 = __float_as_uint(sW[(j * 8 + g) * 260 + k0 + q]);
                unsigned b1 = __float_as_uint(sW[(j * 8 + g) * 260 + k0 + q + 4]);
                mma_tf32(c[j], a, b0, b1);
            }
        }
        // dump partials
        {
            float* rw = sRed + warp * 768;
#pragma unroll
            for (int j = 0; j < 6; j++) {
                rw[g * 48 + j * 8 + 2 * q]           = c[j][0];
                rw[g * 48 + j * 8 + 2 * q + 1]       = c[j][1];
                rw[(g + 8) * 48 + j * 8 + 2 * q]     = c[j][2];
                rw[(g + 8) * 48 + j * 8 + 2 * q + 1] = c[j][3];
            }
        }
        __syncthreads();

        // reduce + GRU pointwise: 256 cells (16 rows x 16 units), 2 per thread
        int ttime = dir ? (1023 - t) : t;
#pragma unroll
        for (int cell = tid; cell < 256; cell += 128) {
            int lr = cell >> 4, uc = cell & 15;
            int o = lr * 48;
            float gr = sRed[o + uc]      + sRed[768 + o + uc]      + sRed[1536 + o + uc]      + sRed[2304 + o + uc];
            float gz = sRed[o + 16 + uc] + sRed[768 + o + 16 + uc] + sRed[1536 + o + 16 + uc] + sRed[2304 + o + 16 + uc];
            float gn = sRed[o + 32 + uc] + sRed[768 + o + 32 + uc] + sRed[1536 + o + 32 + uc] + sRed[2304 + o + 32 + uc];
            int eb = bs * 16 + lr;
            size_t rg = (size_t)eb * 1024 + ttime;
            const float* xirow = xi + rg * 768;
            int gu = u * 16 + uc;
            float xr = xirow[gu], xz = xirow[256 + gu], xn = xirow[512 + gu];
            float rr = sigf(xr + gr + sBhh[uc]);
            float zz = sigf(xz + gz + sBhh[16 + uc]);
            float nn = tanhf(xn + rr * (gn + sBhh[32 + uc]));
            float hp = sH[lr * 260 + gu];
            float hv = (1.0f - zz) * nn + zz * hp;
            buf[(1 - par) * 4096 + lr * 256 + gu] = hv;
            outp[rg * 256 + gu] = hv;
        }
        __syncthreads();
        if (tid == 0) { __threadfence(); atomicAdd(cnt, 1u); }
        target += 16u;
        if (tid == 0) { while (ld_acq(cnt) < target) {} }
        __syncthreads();
    }
}

// ---------------- pooling: mean over S for both encodes, averaged ----------------
__global__ void pool_kernel() {
    int b = blockIdx.x, d = threadIdx.x;
    const float* h0 = g_hn + (size_t)b * 1024 * 256 + d;
    const float* h1 = g_hn + (size_t)(32 + b) * 1024 * 256 + d;
    float s0 = 0.f, s1 = 0.f;
    for (int s = 0; s < 1024; s++) { s0 += h0[(size_t)s * 256]; s1 += h1[(size_t)s * 256]; }
    g_pool[b * 256 + d] = (s0 + s1) * (0.5f / 1024.0f);
}

// ---------------- head: proj to O=64, LN, exact GELU ----------------
__global__ void head_kernel(const float* __restrict__ pw, const float* __restrict__ pb,
                            const float* __restrict__ pg, const float* __restrict__ pbt,
                            float* __restrict__ out) {
    __shared__ float sp[64];
    int b = blockIdx.x, o = threadIdx.x;
    const float* p = g_pool + b * 256;
    float acc = pb[o];
    for (int k = 0; k < 256; k++) acc += p[k] * pw[o * 256 + k];
    sp[o] = acc;
    __syncthreads();
    float m = 0.f;
    for (int k = 0; k < 64; k++) m += sp[k];
    m *= (1.0f / 64.0f);
    float v = 0.f;
    for (int k = 0; k < 64; k++) { float d = sp[k] - m; v += d * d; }
    v *= (1.0f / 64.0f);
    float y = (acc - m) * rsqrtf(v + 1e-5f) * pg[o] + pbt[o];
    out[b * 64 + o] = y * 0.5f * (1.0f + erff(y * 0.70710678118654752f));
}

// ---------------- launch ----------------
extern "C" void kernel_launch(void* const* d_in, const int* in_sizes, int n_in,
                              void* d_out, int out_size) {
    const int*   tok  = (const int*)  d_in[0];
    const float* emb  = (const float*)d_in[1];
    const float* pos  = (const float*)d_in[2];
    const float* lng  = (const float*)d_in[3];
    const float* lnb  = (const float*)d_in[4];
    const float* wihF = (const float*)d_in[5];
    const float* whhF = (const float*)d_in[6];
    const float* bihF = (const float*)d_in[7];
    const float* bhhF = (const float*)d_in[8];
    const float* wihR = (const float*)d_in[9];
    const float* whhR = (const float*)d_in[10];
    const float* bihR = (const float*)d_in[11];
    const float* bhhR = (const float*)d_in[12];
    const float* wg   = (const float*)d_in[13];
    const float* bg   = (const float*)d_in[14];
    const float* wo   = (const float*)d_in[15];
    const float* bo   = (const float*)d_in[16];
    const float* fng  = (const float*)d_in[17];
    const float* fnb  = (const float*)d_in[18];
    const float* pw   = (const float*)d_in[19];
    const float* pb   = (const float*)d_in[20];
    const float* plg  = (const float*)d_in[21];
    const float* plb  = (const float*)d_in[22];

    float* hf; float* hr; float* xif; float* xir; float* hnp; float* hp; void* cntp;
    cudaGetSymbolAddress((void**)&hf,  g_f);
    cudaGetSymbolAddress((void**)&hr,  g_r);
    cudaGetSymbolAddress((void**)&xif, g_xif);
    cudaGetSymbolAddress((void**)&xir, g_xir);
    cudaGetSymbolAddress((void**)&hnp, g_hn);
    cudaGetSymbolAddress((void**)&hp,  g_h);
    cudaGetSymbolAddress(&cntp, g_cnt);

    cudaFuncSetAttribute(rnn_kernel, cudaFuncAttributeMaxDynamicSharedMemorySize, RNN_SMEM);

    embed_kernel<<<65536, 256>>>(tok, emb, pos);

    for (int i = 0; i < 4; i++) {
        const float* wihFi = wihF + (size_t)i * 768 * 256;
        const float* whhFi = whhF + (size_t)i * 768 * 256;
        const float* bihFi = bihF + (size_t)i * 768;
        const float* bhhFi = bhhF + (size_t)i * 768;
        const float* wihRi = wihR + (size_t)i * 768 * 256;
        const float* whhRi = whhR + (size_t)i * 768 * 256;
        const float* bihRi = bihR + (size_t)i * 768;
        const float* bhhRi = bhhR + (size_t)i * 768;
        const float* wgi   = wg + (size_t)i * 256 * 512;
        const float* bgi   = bg + (size_t)i * 256;
        const float* woi   = wo + (size_t)i * 256 * 256;
        const float* boi   = bo + (size_t)i * 256;

        ln_kernel<<<8192, 256>>>(hp, lng + i * 256, lnb + i * 256, hnp);
        gemm_kernel<0><<<dim3(12, 512), 256>>>(hnp, nullptr, wihFi, bihFi, xif);
        gemm_kernel<0><<<dim3(12, 512), 256>>>(hnp, nullptr, wihRi, bihRi, xir);
        cudaMemsetAsync(cntp, 0, 8 * sizeof(unsigned));
        rnn_kernel<<<128, 128, RNN_SMEM>>>(whhFi, whhRi, bhhFi, bhhRi);
        gemm_kernel<1><<<dim3(4, 512), 256>>>(hf, hr, wgi, bgi, hnp);     // hn <- gated c
        gemm_kernel<2><<<dim3(4, 512), 256>>>(hnp, nullptr, woi, boi, hp); // h += c@wo^T+bo
    }

    ln_kernel<<<8192, 256>>>(hp, fng, fnb, hnp);
    pool_kernel<<<32, 256>>>();
    head_kernel<<<32, 64>>>(pw, pb, plg, plb, (float*)d_out);
}

// round 6
// speedup vs baseline: 1.1460x; 1.1460x over previous
#include <cuda_runtime.h>
#include <cuda_bf16.h>
#include <cstdint>
#include <cstddef>

// Problem dims: B=32, S=1024, D=256, L=4, O=64, V=5. Two encodes -> 64 seqs.
#define NROWS 65536          // 2 * 32 * 1024

// ---------------- device scratch (static; no runtime allocation) ----------------
__device__ float g_h  [(size_t)NROWS * 256];   // residual stream
__device__ float g_hn [(size_t)NROWS * 256];   // LN out, later reused as gated "c"
__device__ float g_f  [(size_t)NROWS * 256];   // forward GRU out
__device__ float g_r  [(size_t)NROWS * 256];   // reverse GRU out (natural time order)
__device__ float g_xif[(size_t)NROWS * 768];   // xi forward
__device__ float g_xir[(size_t)NROWS * 768];   // xi reverse
__device__ float g_pool[4 * 32 * 256];         // [s-chunk][batch][d] partial sums
__device__ float g_hbuf[8 * 2 * 16 * 256];     // [group][parity][row16][unit256]
__device__ unsigned g_cnt[8 * 64];             // one counter per 256B (avoid line contention)

// ---------------- helpers ----------------
__device__ __forceinline__ unsigned f2tfu(float x) {
    unsigned u; asm("cvt.rna.tf32.f32 %0, %1;" : "=r"(u) : "f"(x)); return u;
}
__device__ __forceinline__ float f2tff(float x) {
    return __uint_as_float(f2tfu(x));
}
__device__ __forceinline__ void mma_tf32(float* c, const unsigned* a, unsigned b0, unsigned b1) {
    asm volatile(
        "mma.sync.aligned.m16n8k8.row.col.f32.tf32.tf32.f32 "
        "{%0,%1,%2,%3}, {%4,%5,%6,%7}, {%8,%9}, {%0,%1,%2,%3};\n"
        : "+f"(c[0]), "+f"(c[1]), "+f"(c[2]), "+f"(c[3])
        : "r"(a[0]), "r"(a[1]), "r"(a[2]), "r"(a[3]), "r"(b0), "r"(b1));
}
__device__ __forceinline__ unsigned ld_acq(const unsigned* p) {
    unsigned v; asm volatile("ld.global.acquire.gpu.u32 %0, [%1];" : "=r"(v) : "l"(p)); return v;
}
__device__ __forceinline__ void red_rel(unsigned* p, unsigned v) {
    asm volatile("red.release.gpu.global.add.u32 [%0], %1;" :: "l"(p), "r"(v) : "memory");
}
__device__ __forceinline__ float sigf(float x) { return 1.0f / (1.0f + expf(-x)); }

// ---------------- embedding (both encodes) ----------------
// row = e*32768 + b*1024 + s ; e=1 is reverse-complement sequence
__global__ void embed_kernel(const int* __restrict__ tok, const float* __restrict__ emb,
                             const float* __restrict__ pos) {
    int bid = blockIdx.x;
    int d = threadIdx.x;
    int e = bid >> 15, rem = bid & 32767, b = rem >> 10, s = rem & 1023;
    int t;
    if (e == 0) t = tok[b * 1024 + s];
    else { int t0 = tok[b * 1024 + (1023 - s)]; t = (t0 < 4) ? (3 - t0) : 4; }
    g_h[(size_t)bid * 256 + d] = emb[t * 256 + d] + pos[s * 256 + d];
}

// ---------------- layernorm over D=256 (one warp per row, 8 rows per CTA) ----------------
__global__ void ln_kernel(const float* __restrict__ X, const float* __restrict__ gw,
                          const float* __restrict__ gb, float* __restrict__ Y) {
    int warp = threadIdx.x >> 5, lane = threadIdx.x & 31;
    int row = blockIdx.x * 8 + warp;
    const float* x = X + (size_t)row * 256;
    float v[8];
#pragma unroll
    for (int i = 0; i < 8; i++) v[i] = x[lane + i * 32];
    float s = 0.f;
#pragma unroll
    for (int i = 0; i < 8; i++) s += v[i];
#pragma unroll
    for (int o = 16; o > 0; o >>= 1) s += __shfl_xor_sync(0xffffffffu, s, o);
    float m = s * (1.0f / 256.0f);
    float q = 0.f;
#pragma unroll
    for (int i = 0; i < 8; i++) { float d = v[i] - m; q += d * d; }
#pragma unroll
    for (int o = 16; o > 0; o >>= 1) q += __shfl_xor_sync(0xffffffffu, q, o);
    float rs = rsqrtf(q * (1.0f / 256.0f) + 1e-5f);
    float* y = Y + (size_t)row * 256;
#pragma unroll
    for (int i = 0; i < 8; i++) {
        int d = lane + i * 32;
        y[d] = (v[i] - m) * rs * gw[d] + gb[d];
    }
}

// ---------------- tf32 GEMM: out = act(A @ W^T + bias) ----------------
// MODE 0: xi   (K=256, N=768, plain + bias)
// MODE 1: gate (K=512: k<256 from A=f, k>=256 from A2=r; N=256; out = g*f+(1-g)*r)
// MODE 2: oproj(K=256, N=256; out += val + bias  (residual))
template <int MODE>
__global__ __launch_bounds__(256)
void gemm_kernel(const float* __restrict__ A, const float* __restrict__ A2,
                 const float* __restrict__ W, const float* __restrict__ bias,
                 float* __restrict__ out) {
    __shared__ float sA[128 * 36];
    __shared__ float sB[64 * 36];
    const int KT  = (MODE == 1) ? 512 : 256;
    const int WLD = (MODE == 1) ? 512 : 256;
    int tid = threadIdx.x, lane = tid & 31, warp = tid >> 5;
    int wm = warp >> 1, wn = warp & 1;
    int rowBase = blockIdx.y * 128;
    int colBase = blockIdx.x * 64;
    int g = lane >> 2, q = lane & 3;

    float acc[2][4][4];
#pragma unroll
    for (int a = 0; a < 2; a++)
#pragma unroll
        for (int b = 0; b < 4; b++)
#pragma unroll
            for (int c = 0; c < 4; c++) acc[a][b][c] = 0.f;

    float4 ra[4], rb[2];
    auto ldA = [&](int k0, float4* dst) {
        const float* Asrc = (MODE == 1 && k0 >= 256) ? A2 : A;
        int kA = (MODE == 1) ? (k0 & 255) : k0;
#pragma unroll
        for (int i = 0; i < 4; i++) {
            int flat = tid + i * 256;
            int r = flat >> 3, c4 = flat & 7;
            dst[i] = *(const float4*)&Asrc[(size_t)(rowBase + r) * 256 + kA + c4 * 4];
        }
    };
    auto ldB = [&](int k0, float4* dst) {
#pragma unroll
        for (int i = 0; i < 2; i++) {
            int flat = tid + i * 256;
            int r = flat >> 3, c4 = flat & 7;
            dst[i] = *(const float4*)&W[(size_t)(colBase + r) * WLD + k0 + c4 * 4];
        }
    };
    ldA(0, ra); ldB(0, rb);

    for (int k0 = 0; k0 < KT; k0 += 32) {
        // stage current chunk (vectorized STS.128, conflict-free with stride-36 pad)
#pragma unroll
        for (int i = 0; i < 4; i++) {
            int flat = tid + i * 256;
            int r = flat >> 3, c4 = flat & 7;
            float4 w;
            w.x = f2tff(ra[i].x); w.y = f2tff(ra[i].y);
            w.z = f2tff(ra[i].z); w.w = f2tff(ra[i].w);
            *(float4*)&sA[r * 36 + c4 * 4] = w;
        }
#pragma unroll
        for (int i = 0; i < 2; i++) {
            int flat = tid + i * 256;
            int r = flat >> 3, c4 = flat & 7;
            float4 w;
            w.x = f2tff(rb[i].x); w.y = f2tff(rb[i].y);
            w.z = f2tff(rb[i].z); w.w = f2tff(rb[i].w);
            *(float4*)&sB[r * 36 + c4 * 4] = w;
        }
        __syncthreads();
        // prefetch next chunk while MMAs run
        if (k0 + 32 < KT) { ldA(k0 + 32, ra); ldB(k0 + 32, rb); }
#pragma unroll
        for (int kk = 0; kk < 4; kk++) {
            int ko = kk * 8;
            unsigned a[2][4];
#pragma unroll
            for (int mt = 0; mt < 2; mt++) {
                int rb2 = wm * 32 + mt * 16;
                a[mt][0] = __float_as_uint(sA[(rb2 + g) * 36 + ko + q]);
                a[mt][1] = __float_as_uint(sA[(rb2 + g + 8) * 36 + ko + q]);
                a[mt][2] = __float_as_uint(sA[(rb2 + g) * 36 + ko + q + 4]);
                a[mt][3] = __float_as_uint(sA[(rb2 + g + 8) * 36 + ko + q + 4]);
            }
#pragma unroll
            for (int nt = 0; nt < 4; nt++) {
                int nb = wn * 32 + nt * 8;
                unsigned b0 = __float_as_uint(sB[(nb + g) * 36 + ko + q]);
                unsigned b1 = __float_as_uint(sB[(nb + g) * 36 + ko + q + 4]);
                mma_tf32(acc[0][nt], a[0], b0, b1);
                mma_tf32(acc[1][nt], a[1], b0, b1);
            }
        }
        __syncthreads();
    }
    // epilogue
#pragma unroll
    for (int mt = 0; mt < 2; mt++)
#pragma unroll
        for (int nt = 0; nt < 4; nt++)
#pragma unroll
            for (int i = 0; i < 4; i++) {
                int row = rowBase + wm * 32 + mt * 16 + g + ((i & 2) ? 8 : 0);
                int coln = colBase + wn * 32 + nt * 8 + 2 * q + (i & 1);
                float val = acc[mt][nt][i] + bias[coln];
                if (MODE == 0) {
                    out[(size_t)row * 768 + coln] = val;
                } else if (MODE == 1) {
                    float gg = sigf(val);
                    float fv = A [(size_t)row * 256 + coln];
                    float rv = A2[(size_t)row * 256 + coln];
                    out[(size_t)row * 256 + coln] = gg * fv + (1.0f - gg) * rv;
                } else {
                    out[(size_t)row * 256 + coln] += val;
                }
            }
}

// ---------------- persistent bidirectional GRU scan ----------------
// 128 CTAs: dir(2) x batch-slice(4, 16 rows) x unit-slice(16, 16 hidden units).
// Group = dir*4+bs (16 CTAs) exchanges h via double-buffered g_hbuf.
// Barrier: bar.sync + red.release counter + ld.acquire poll (no threadfence,
// streaming outputs deliberately written AFTER the release).
#define RNN_SMEM ((48*260 + 16*260 + 4*16*48 + 48) * 4)

__global__ __launch_bounds__(128)
void rnn_kernel(const float* __restrict__ whhF, const float* __restrict__ whhR,
                const float* __restrict__ bhhF, const float* __restrict__ bhhR) {
    extern __shared__ float sm[];
    float* sW   = sm;                 // 48 x 260 (tf32)
    float* sH   = sW + 48 * 260;      // 16 x 260 (full fp32 h tile)
    float* sRed = sH + 16 * 260;      // 4 warps x 16 x 48 partials
    float* sBhh = sRed + 4 * 16 * 48; // 48

    int cta = blockIdx.x;
    int dir = cta >> 6, rem = cta & 63, bs = rem >> 4, u = rem & 15;
    int group = dir * 4 + bs;
    const float* W    = dir ? whhR : whhF;
    const float* bhh  = dir ? bhhR : bhhF;
    const float* xi   = dir ? g_xir : g_xif;
    float*       outp = dir ? g_r   : g_f;
    float*    buf = g_hbuf + (size_t)group * 8192;   // 2 x 16 x 256
    unsigned* cnt = &g_cnt[group * 64];

    int tid = threadIdx.x, lane = tid & 31, warp = tid >> 5;
    int g = lane >> 2, q = lane & 3;

    // load weight slice (gate rows: r,z,n for units u*16..u*16+15) -> tf32 in SMEM
    for (int idx = tid; idx < 48 * 256; idx += 128) {
        int rI = idx >> 8, k = idx & 255;
        int grow = (rI >> 4) * 256 + u * 16 + (rI & 15);
        sW[rI * 260 + k] = f2tff(W[(size_t)grow * 256 + k]);
    }
    if (tid < 48) {
        int grow = (tid >> 4) * 256 + u * 16 + (tid & 15);
        sBhh[tid] = bhh[grow];
    }
    // zero my block of h buffer parity 0
    for (int idx = tid; idx < 256; idx += 128) {
        int lr = idx >> 4, c = idx & 15;
        buf[lr * 256 + u * 16 + c] = 0.f;
    }
    __syncthreads();
    if (tid == 0) red_rel(cnt, 1u);
    unsigned target = 16u;
    if (tid == 0) { while (ld_acq(cnt) < target) {} }
    __syncthreads();

    // per-thread cell mapping for reduce/pointwise (2 cells: tid and tid+128)
    int uc = tid & 15;
    int gu = u * 16 + uc;
    int lr0 = tid >> 4;        // 0..7
    int lr1 = lr0 + 8;         // 8..15

    for (int t = 0; t < 1024; t++) {
        int par = t & 1;
        int ttime = dir ? (1023 - t) : t;
        size_t row0 = (size_t)(bs * 16 + lr0) * 1024 + ttime;
        size_t row1 = (size_t)(bs * 16 + lr1) * 1024 + ttime;

        // prefetch xi for this step (DRAM latency off the critical path)
        const float* x0 = xi + row0 * 768;
        const float* x1 = xi + row1 * 768;
        float xr0 = x0[gu], xz0 = x0[256 + gu], xn0 = x0[512 + gu];
        float xr1 = x1[gu], xz1 = x1[256 + gu], xn1 = x1[512 + gu];

        // stage full h tile (16 rows x 256) for my batch slice
        for (int idx = tid; idx < 1024; idx += 128) {
            int lr = idx >> 6, c4 = idx & 63;
            float4 v = *(const float4*)&buf[par * 4096 + lr * 256 + c4 * 4];
            float* d = &sH[lr * 260 + c4 * 4];
            d[0] = v.x; d[1] = v.y; d[2] = v.z; d[3] = v.w;
        }
        __syncthreads();

        // MMA: 16x48 = h(16x256) @ Wslice^T(48x256), k split across 4 warps
        float c[6][4];
#pragma unroll
        for (int j = 0; j < 6; j++)
#pragma unroll
            for (int i = 0; i < 4; i++) c[j][i] = 0.f;
        int kbase = warp * 64;
#pragma unroll
        for (int ks = 0; ks < 8; ks++) {
            int k0 = kbase + ks * 8;
            unsigned a[4];
            a[0] = f2tfu(sH[g * 260 + k0 + q]);
            a[1] = f2tfu(sH[(g + 8) * 260 + k0 + q]);
            a[2] = f2tfu(sH[g * 260 + k0 + q + 4]);
            a[3] = f2tfu(sH[(g + 8) * 260 + k0 + q + 4]);
#pragma unroll
            for (int j = 0; j < 6; j++) {
                unsigned b0 = __float_as_uint(sW[(j * 8 + g) * 260 + k0 + q]);
                unsigned b1 = __float_as_uint(sW[(j * 8 + g) * 260 + k0 + q + 4]);
                mma_tf32(c[j], a, b0, b1);
            }
        }
        // dump partials
        {
            float* rw = sRed + warp * 768;
#pragma unroll
            for (int j = 0; j < 6; j++) {
                rw[g * 48 + j * 8 + 2 * q]           = c[j][0];
                rw[g * 48 + j * 8 + 2 * q + 1]       = c[j][1];
                rw[(g + 8) * 48 + j * 8 + 2 * q]     = c[j][2];
                rw[(g + 8) * 48 + j * 8 + 2 * q + 1] = c[j][3];
            }
        }
        __syncthreads();

        // reduce + GRU pointwise for the 2 cells owned by this thread
        float hv0, hv1;
        {
            int o = lr0 * 48;
            float gr = sRed[o + uc]      + sRed[768 + o + uc]      + sRed[1536 + o + uc]      + sRed[2304 + o + uc];
            float gz = sRed[o + 16 + uc] + sRed[768 + o + 16 + uc] + sRed[1536 + o + 16 + uc] + sRed[2304 + o + 16 + uc];
            float gn = sRed[o + 32 + uc] + sRed[768 + o + 32 + uc] + sRed[1536 + o + 32 + uc] + sRed[2304 + o + 32 + uc];
            float rr = sigf(xr0 + gr + sBhh[uc]);
            float zz = sigf(xz0 + gz + sBhh[16 + uc]);
            float nn = tanhf(xn0 + rr * (gn + sBhh[32 + uc]));
            float hp = sH[lr0 * 260 + gu];
            hv0 = (1.0f - zz) * nn + zz * hp;
        }
        {
            int o = lr1 * 48;
            float gr = sRed[o + uc]      + sRed[768 + o + uc]      + sRed[1536 + o + uc]      + sRed[2304 + o + uc];
            float gz = sRed[o + 16 + uc] + sRed[768 + o + 16 + uc] + sRed[1536 + o + 16 + uc] + sRed[2304 + o + 16 + uc];
            float gn = sRed[o + 32 + uc] + sRed[768 + o + 32 + uc] + sRed[1536 + o + 32 + uc] + sRed[2304 + o + 32 + uc];
            float rr = sigf(xr1 + gr + sBhh[uc]);
            float zz = sigf(xz1 + gz + sBhh[16 + uc]);
            float nn = tanhf(xn1 + rr * (gn + sBhh[32 + uc]));
            float hp = sH[lr1 * 260 + gu];
            hv1 = (1.0f - zz) * nn + zz * hp;
        }
        // publish next-h slice (must precede release)
        buf[(1 - par) * 4096 + lr0 * 256 + gu] = hv0;
        buf[(1 - par) * 4096 + lr1 * 256 + gu] = hv1;
        __syncthreads();                    // all buf writes ordered before release
        if (tid == 0) red_rel(cnt, 1u);
        // streaming outputs AFTER the release: not consumed until kernel end
        outp[row0 * 256 + gu] = hv0;
        outp[row1 * 256 + gu] = hv1;
        target += 16u;
        if (tid == 0) { while (ld_acq(cnt) < target) {} }
        __syncthreads();
    }
}

// ---------------- pooling: partial mean over S (4 chunks), both encodes ----------------
__global__ void pool_kernel() {
    int b = blockIdx.x, cch = blockIdx.y, d = threadIdx.x;
    const float* h0 = g_hn + ((size_t)b * 1024 + cch * 256) * 256 + d;
    const float* h1 = g_hn + ((size_t)(32 + b) * 1024 + cch * 256) * 256 + d;
    float s = 0.f;
#pragma unroll 4
    for (int si = 0; si < 256; si++) s += h0[(size_t)si * 256] + h1[(size_t)si * 256];
    g_pool[((size_t)cch * 32 + b) * 256 + d] = s;
}

// ---------------- head: proj to O=64, LN, exact GELU ----------------
__global__ void head_kernel(const float* __restrict__ pw, const float* __restrict__ pb,
                            const float* __restrict__ pg, const float* __restrict__ pbt,
                            float* __restrict__ out) {
    __shared__ float pooled[256];
    __shared__ float sp[64];
    int b = blockIdx.x, o = threadIdx.x;   // 64 threads
    for (int k = o; k < 256; k += 64) {
        float s = 0.f;
#pragma unroll
        for (int cch = 0; cch < 4; cch++) s += g_pool[((size_t)cch * 32 + b) * 256 + k];
        pooled[k] = s * (0.5f / 1024.0f);
    }
    __syncthreads();
    float acc = pb[o];
    for (int k = 0; k < 256; k++) acc += pooled[k] * pw[o * 256 + k];
    sp[o] = acc;
    __syncthreads();
    float m = 0.f;
    for (int k = 0; k < 64; k++) m += sp[k];
    m *= (1.0f / 64.0f);
    float v = 0.f;
    for (int k = 0; k < 64; k++) { float d = sp[k] - m; v += d * d; }
    v *= (1.0f / 64.0f);
    float y = (acc - m) * rsqrtf(v + 1e-5f) * pg[o] + pbt[o];
    out[b * 64 + o] = y * 0.5f * (1.0f + erff(y * 0.70710678118654752f));
}

// ---------------- launch ----------------
extern "C" void kernel_launch(void* const* d_in, const int* in_sizes, int n_in,
                              void* d_out, int out_size) {
    const int*   tok  = (const int*)  d_in[0];
    const float* emb  = (const float*)d_in[1];
    const float* pos  = (const float*)d_in[2];
    const float* lng  = (const float*)d_in[3];
    const float* lnb  = (const float*)d_in[4];
    const float* wihF = (const float*)d_in[5];
    const float* whhF = (const float*)d_in[6];
    const float* bihF = (const float*)d_in[7];
    const float* bhhF = (const float*)d_in[8];
    const float* wihR = (const float*)d_in[9];
    const float* whhR = (const float*)d_in[10];
    const float* bihR = (const float*)d_in[11];
    const float* bhhR = (const float*)d_in[12];
    const float* wg   = (const float*)d_in[13];
    const float* bg   = (const float*)d_in[14];
    const float* wo   = (const float*)d_in[15];
    const float* bo   = (const float*)d_in[16];
    const float* fng  = (const float*)d_in[17];
    const float* fnb  = (const float*)d_in[18];
    const float* pw   = (const float*)d_in[19];
    const float* pb   = (const float*)d_in[20];
    const float* plg  = (const float*)d_in[21];
    const float* plb  = (const float*)d_in[22];

    float* hf; float* hr; float* xif; float* xir; float* hnp; float* hp; void* cntp;
    cudaGetSymbolAddress((void**)&hf,  g_f);
    cudaGetSymbolAddress((void**)&hr,  g_r);
    cudaGetSymbolAddress((void**)&xif, g_xif);
    cudaGetSymbolAddress((void**)&xir, g_xir);
    cudaGetSymbolAddress((void**)&hnp, g_hn);
    cudaGetSymbolAddress((void**)&hp,  g_h);
    cudaGetSymbolAddress(&cntp, g_cnt);

    cudaFuncSetAttribute(rnn_kernel, cudaFuncAttributeMaxDynamicSharedMemorySize, RNN_SMEM);

    embed_kernel<<<65536, 256>>>(tok, emb, pos);

    for (int i = 0; i < 4; i++) {
        const float* wihFi = wihF + (size_t)i * 768 * 256;
        const float* whhFi = whhF + (size_t)i * 768 * 256;
        const float* bihFi = bihF + (size_t)i * 768;
        const float* bhhFi = bhhF + (size_t)i * 768;
        const float* wihRi = wihR + (size_t)i * 768 * 256;
        const float* whhRi = whhR + (size_t)i * 768 * 256;
        const float* bihRi = bihR + (size_t)i * 768;
        const float* bhhRi = bhhR + (size_t)i * 768;
        const float* wgi   = wg + (size_t)i * 256 * 512;
        const float* bgi   = bg + (size_t)i * 256;
        const float* woi   = wo + (size_t)i * 256 * 256;
        const float* boi   = bo + (size_t)i * 256;

        ln_kernel<<<8192, 256>>>(hp, lng + i * 256, lnb + i * 256, hnp);
        gemm_kernel<0><<<dim3(12, 512), 256>>>(hnp, nullptr, wihFi, bihFi, xif);
        gemm_kernel<0><<<dim3(12, 512), 256>>>(hnp, nullptr, wihRi, bihRi, xir);
        cudaMemsetAsync(cntp, 0, 8 * 64 * sizeof(unsigned));
        rnn_kernel<<<128, 128, RNN_SMEM>>>(whhFi, whhRi, bhhFi, bhhRi);
        gemm_kernel<1><<<dim3(4, 512), 256>>>(hf, hr, wgi, bgi, hnp);     // hn <- gated c
        gemm_kernel<2><<<dim3(4, 512), 256>>>(hnp, nullptr, woi, boi, hp); // h += c@wo^T+bo
    }

    ln_kernel<<<8192, 256>>>(hp, fng, fnb, hnp);
    pool_kernel<<<dim3(32, 4), 256>>>();
    head_kernel<<<32, 64>>>(pw, pb, plg, plb, (float*)d_out);
}

// round 8
// speedup vs baseline: 1.4619x; 1.2756x over previous
#include <cuda_runtime.h>
#include <cuda_bf16.h>
#include <cstdint>
#include <cstddef>

// Problem dims: B=32, S=1024, D=256, L=4, O=64, V=5. Two encodes -> 64 seqs.
#define NROWS 65536          // 2 * 32 * 1024

// ---------------- device scratch (static; no runtime allocation) ----------------
__device__ float g_h  [(size_t)NROWS * 256];   // residual stream
__device__ float g_hn [(size_t)NROWS * 256];   // LN out, later reused as gated "c"
__device__ float g_f  [(size_t)NROWS * 256];   // forward GRU out
__device__ float g_r  [(size_t)NROWS * 256];   // reverse GRU out (natural time order)
__device__ float g_xif[(size_t)NROWS * 768];   // xi forward
__device__ float g_xir[(size_t)NROWS * 768];   // xi reverse
__device__ float g_pool[4 * 32 * 256];         // [s-chunk][batch][d] partial sums
__device__ float g_hbuf[8 * 2 * 16 * 256];     // [group][parity][row16][unit256]
__device__ unsigned g_cnt[8 * 64];             // one counter per 256B (avoid line contention)

// ---------------- helpers ----------------
__device__ __forceinline__ unsigned f2tfu(float x) {
    unsigned u; asm("cvt.rna.tf32.f32 %0, %1;" : "=r"(u) : "f"(x)); return u;
}
__device__ __forceinline__ float f2tff(float x) {
    return __uint_as_float(f2tfu(x));
}
__device__ __forceinline__ void mma_tf32(float* c, const unsigned* a, unsigned b0, unsigned b1) {
    asm volatile(
        "mma.sync.aligned.m16n8k8.row.col.f32.tf32.tf32.f32 "
        "{%0,%1,%2,%3}, {%4,%5,%6,%7}, {%8,%9}, {%0,%1,%2,%3};\n"
        : "+f"(c[0]), "+f"(c[1]), "+f"(c[2]), "+f"(c[3])
        : "r"(a[0]), "r"(a[1]), "r"(a[2]), "r"(a[3]), "r"(b0), "r"(b1));
}
__device__ __forceinline__ unsigned ld_acq(const unsigned* p) {
    unsigned v; asm volatile("ld.global.acquire.gpu.u32 %0, [%1];" : "=r"(v) : "l"(p)); return v;
}
__device__ __forceinline__ void red_rel(unsigned* p, unsigned v) {
    asm volatile("red.release.gpu.global.add.u32 [%0], %1;" :: "l"(p), "r"(v) : "memory");
}
__device__ __forceinline__ float sigf(float x) { return 1.0f / (1.0f + expf(-x)); }

// ---------------- embedding (both encodes) ----------------
// row = e*32768 + b*1024 + s ; e=1 is reverse-complement sequence
__global__ void embed_kernel(const int* __restrict__ tok, const float* __restrict__ emb,
                             const float* __restrict__ pos) {
    int bid = blockIdx.x;
    int d = threadIdx.x;
    int e = bid >> 15, rem = bid & 32767, b = rem >> 10, s = rem & 1023;
    int t;
    if (e == 0) t = tok[b * 1024 + s];
    else { int t0 = tok[b * 1024 + (1023 - s)]; t = (t0 < 4) ? (3 - t0) : 4; }
    g_h[(size_t)bid * 256 + d] = emb[t * 256 + d] + pos[s * 256 + d];
}

// ---------------- layernorm over D=256 (one warp per row, 8 rows per CTA) ----------------
__global__ void ln_kernel(const float* __restrict__ X, const float* __restrict__ gw,
                          const float* __restrict__ gb, float* __restrict__ Y) {
    int warp = threadIdx.x >> 5, lane = threadIdx.x & 31;
    int row = blockIdx.x * 8 + warp;
    const float* x = X + (size_t)row * 256;
    float v[8];
#pragma unroll
    for (int i = 0; i < 8; i++) v[i] = x[lane + i * 32];
    float s = 0.f;
#pragma unroll
    for (int i = 0; i < 8; i++) s += v[i];
#pragma unroll
    for (int o = 16; o > 0; o >>= 1) s += __shfl_xor_sync(0xffffffffu, s, o);
    float m = s * (1.0f / 256.0f);
    float q = 0.f;
#pragma unroll
    for (int i = 0; i < 8; i++) { float d = v[i] - m; q += d * d; }
#pragma unroll
    for (int o = 16; o > 0; o >>= 1) q += __shfl_xor_sync(0xffffffffu, q, o);
    float rs = rsqrtf(q * (1.0f / 256.0f) + 1e-5f);
    float* y = Y + (size_t)row * 256;
#pragma unroll
    for (int i = 0; i < 8; i++) {
        int d = lane + i * 32;
        y[d] = (v[i] - m) * rs * gw[d] + gb[d];
    }
}

// ---------------- tf32 GEMM: out = act(A @ W^T + bias) ----------------
// MODE 0: xi   (K=256, N=768, plain + bias)
// MODE 1: gate (K=512: k<256 from A=f, k>=256 from A2=r; N=256; out = g*f+(1-g)*r)
// MODE 2: oproj(K=256, N=256; out += val + bias  (residual))
template <int MODE>
__global__ __launch_bounds__(256)
void gemm_kernel(const float* __restrict__ A, const float* __restrict__ A2,
                 const float* __restrict__ W, const float* __restrict__ bias,
                 float* __restrict__ out) {
    __shared__ float sA[128 * 36];
    __shared__ float sB[64 * 36];
    const int KT  = (MODE == 1) ? 512 : 256;
    const int WLD = (MODE == 1) ? 512 : 256;
    int tid = threadIdx.x, lane = tid & 31, warp = tid >> 5;
    int wm = warp >> 1, wn = warp & 1;
    int rowBase = blockIdx.y * 128;
    int colBase = blockIdx.x * 64;
    int g = lane >> 2, q = lane & 3;

    float acc[2][4][4];
#pragma unroll
    for (int a = 0; a < 2; a++)
#pragma unroll
        for (int b = 0; b < 4; b++)
#pragma unroll
            for (int c = 0; c < 4; c++) acc[a][b][c] = 0.f;

    for (int k0 = 0; k0 < KT; k0 += 32) {
        const float* Asrc = (MODE == 1 && k0 >= 256) ? A2 : A;
        int kA = (MODE == 1) ? (k0 & 255) : k0;
#pragma unroll
        for (int i = 0; i < 4; i++) {
            int flat = tid + i * 256;          // 1024 float4 total
            int r = flat >> 3, c4 = flat & 7;
            float4 v = *(const float4*)&Asrc[(size_t)(rowBase + r) * 256 + kA + c4 * 4];
            float4 w;
            w.x = f2tff(v.x); w.y = f2tff(v.y); w.z = f2tff(v.z); w.w = f2tff(v.w);
            *(float4*)&sA[r * 36 + c4 * 4] = w;
        }
#pragma unroll
        for (int i = 0; i < 2; i++) {
            int flat = tid + i * 256;          // 512 float4 total
            int r = flat >> 3, c4 = flat & 7;
            float4 v = *(const float4*)&W[(size_t)(colBase + r) * WLD + k0 + c4 * 4];
            float4 w;
            w.x = f2tff(v.x); w.y = f2tff(v.y); w.z = f2tff(v.z); w.w = f2tff(v.w);
            *(float4*)&sB[r * 36 + c4 * 4] = w;
        }
        __syncthreads();
#pragma unroll
        for (int kk = 0; kk < 4; kk++) {
            int ko = kk * 8;
            unsigned a[2][4];
#pragma unroll
            for (int mt = 0; mt < 2; mt++) {
                int rb2 = wm * 32 + mt * 16;
                a[mt][0] = __float_as_uint(sA[(rb2 + g) * 36 + ko + q]);
                a[mt][1] = __float_as_uint(sA[(rb2 + g + 8) * 36 + ko + q]);
                a[mt][2] = __float_as_uint(sA[(rb2 + g) * 36 + ko + q + 4]);
                a[mt][3] = __float_as_uint(sA[(rb2 + g + 8) * 36 + ko + q + 4]);
            }
#pragma unroll
            for (int nt = 0; nt < 4; nt++) {
                int nb = wn * 32 + nt * 8;
                unsigned b0 = __float_as_uint(sB[(nb + g) * 36 + ko + q]);
                unsigned b1 = __float_as_uint(sB[(nb + g) * 36 + ko + q + 4]);
                mma_tf32(acc[0][nt], a[0], b0, b1);
                mma_tf32(acc[1][nt], a[1], b0, b1);
            }
        }
        __syncthreads();
    }
    // epilogue
#pragma unroll
    for (int mt = 0; mt < 2; mt++)
#pragma unroll
        for (int nt = 0; nt < 4; nt++)
#pragma unroll
            for (int i = 0; i < 4; i++) {
                int row = rowBase + wm * 32 + mt * 16 + g + ((i & 2) ? 8 : 0);
                int coln = colBase + wn * 32 + nt * 8 + 2 * q + (i & 1);
                float val = acc[mt][nt][i] + bias[coln];
                if (MODE == 0) {
                    out[(size_t)row * 768 + coln] = val;
                } else if (MODE == 1) {
                    float gg = sigf(val);
                    float fv = A [(size_t)row * 256 + coln];
                    float rv = A2[(size_t)row * 256 + coln];
                    out[(size_t)row * 256 + coln] = gg * fv + (1.0f - gg) * rv;
                } else {
                    out[(size_t)row * 256 + coln] += val;
                }
            }
}

// ---------------- persistent bidirectional GRU scan ----------------
// 128 CTAs: dir(2) x batch-slice(4, 16 rows) x unit-slice(16, 16 hidden units).
// Group = dir*4+bs (16 CTAs) exchanges h via double-buffered g_hbuf.
// Whh fragments live in REGISTERS (96/thread) -> no b-LDS in the step loop.
// sH holds tf32-converted h (MMA operand); hp for the GRU blend is re-read
// fp32-exact from g_hbuf (L1 hit).
#define RNN_SMEM ((48*260 + 16*260 + 4*16*48 + 48) * 4)

__global__ __launch_bounds__(128)
void rnn_kernel(const float* __restrict__ whhF, const float* __restrict__ whhR,
                const float* __restrict__ bhhF, const float* __restrict__ bhhR) {
    extern __shared__ float sm[];
    float* sW   = sm;                 // 48 x 260 (tf32)  [init only]
    float* sH   = sW + 48 * 260;      // 16 x 260 (tf32 h tile)
    float* sRed = sH + 16 * 260;      // 4 warps x 16 x 48 partials
    float* sBhh = sRed + 4 * 16 * 48; // 48

    int cta = blockIdx.x;
    int dir = cta >> 6, rem = cta & 63, bs = rem >> 4, u = rem & 15;
    int group = dir * 4 + bs;
    const float* W    = dir ? whhR : whhF;
    const float* bhh  = dir ? bhhR : bhhF;
    const float* xi   = dir ? g_xir : g_xif;
    float*       outp = dir ? g_r   : g_f;
    float*    buf = g_hbuf + (size_t)group * 8192;   // 2 x 16 x 256
    unsigned* cnt = &g_cnt[group * 64];

    int tid = threadIdx.x, lane = tid & 31, warp = tid >> 5;
    int g = lane >> 2, q = lane & 3;

    // load weight slice (gate rows: r,z,n for units u*16..u*16+15) -> tf32 in SMEM
    for (int idx = tid; idx < 48 * 256; idx += 128) {
        int rI = idx >> 8, k = idx & 255;
        int grow = (rI >> 4) * 256 + u * 16 + (rI & 15);
        sW[rI * 260 + k] = f2tff(W[(size_t)grow * 256 + k]);
    }
    if (tid < 48) {
        int grow = (tid >> 4) * 256 + u * 16 + (tid & 15);
        sBhh[tid] = bhh[grow];
    }
    // zero my block of h buffer parity 0
    for (int idx = tid; idx < 256; idx += 128) {
        int lr = idx >> 4, c = idx & 15;
        buf[lr * 256 + u * 16 + c] = 0.f;
    }
    __syncthreads();

    // hoist Whh fragments into registers (loop-invariant over all 1024 steps)
    int kbase = warp * 64;
    unsigned bfr[8][6][2];
#pragma unroll
    for (int ks = 0; ks < 8; ks++) {
        int k0 = kbase + ks * 8;
#pragma unroll
        for (int j = 0; j < 6; j++) {
            bfr[ks][j][0] = __float_as_uint(sW[(j * 8 + g) * 260 + k0 + q]);
            bfr[ks][j][1] = __float_as_uint(sW[(j * 8 + g) * 260 + k0 + q + 4]);
        }
    }

    if (tid == 0) red_rel(cnt, 1u);
    unsigned target = 16u;
    if (tid == 0) { while (ld_acq(cnt) < target) {} }
    __syncthreads();

    // per-thread cell mapping for reduce/pointwise (2 cells)
    int uc = tid & 15;
    int gu = u * 16 + uc;
    int lr0 = tid >> 4;        // 0..7
    int lr1 = lr0 + 8;         // 8..15

    // xi prefetch for t=0
    float xr0, xz0, xn0, xr1, xz1, xn1;
    {
        int tt = dir ? 1023 : 0;
        const float* x0 = xi + ((size_t)(bs * 16 + lr0) * 1024 + tt) * 768;
        const float* x1 = xi + ((size_t)(bs * 16 + lr1) * 1024 + tt) * 768;
        xr0 = x0[gu]; xz0 = x0[256 + gu]; xn0 = x0[512 + gu];
        xr1 = x1[gu]; xz1 = x1[256 + gu]; xn1 = x1[512 + gu];
    }

    for (int t = 0; t < 1024; t++) {
        int par = t & 1;
        int ttime = dir ? (1023 - t) : t;
        size_t row0 = (size_t)(bs * 16 + lr0) * 1024 + ttime;
        size_t row1 = (size_t)(bs * 16 + lr1) * 1024 + ttime;

        // fp32-exact previous h for the z-blend (L1/L2 hit)
        float hp0 = buf[par * 4096 + lr0 * 256 + gu];
        float hp1 = buf[par * 4096 + lr1 * 256 + gu];

        // stage FULL h tile (16 x 256 = 1024 float4) as tf32, 8 float4/thread
#pragma unroll
        for (int it = 0; it < 8; it++) {
            int idx = tid + it * 128;          // 0..1023
            int lr = idx >> 6, c4 = idx & 63;
            float4 v = *(const float4*)&buf[par * 4096 + lr * 256 + c4 * 4];
            float4 w;
            w.x = f2tff(v.x); w.y = f2tff(v.y); w.z = f2tff(v.z); w.w = f2tff(v.w);
            *(float4*)&sH[lr * 260 + c4 * 4] = w;
        }
        __syncthreads();

        // MMA: 16x48 = h(16x256) @ Wslice^T(48x256), k split across 4 warps,
        // b operands register-resident
        float c[6][4];
#pragma unroll
        for (int j = 0; j < 6; j++)
#pragma unroll
            for (int i = 0; i < 4; i++) c[j][i] = 0.f;
#pragma unroll
        for (int ks = 0; ks < 8; ks++) {
            int k0 = kbase + ks * 8;
            unsigned a[4];
            a[0] = __float_as_uint(sH[g * 260 + k0 + q]);
            a[1] = __float_as_uint(sH[(g + 8) * 260 + k0 + q]);
            a[2] = __float_as_uint(sH[g * 260 + k0 + q + 4]);
            a[3] = __float_as_uint(sH[(g + 8) * 260 + k0 + q + 4]);
#pragma unroll
            for (int j = 0; j < 6; j++)
                mma_tf32(c[j], a, bfr[ks][j][0], bfr[ks][j][1]);
        }
        // dump partials (float2-vectorized)
        {
            float* rw = sRed + warp * 768;
#pragma unroll
            for (int j = 0; j < 6; j++) {
                *(float2*)&rw[g * 48 + j * 8 + 2 * q]       = make_float2(c[j][0], c[j][1]);
                *(float2*)&rw[(g + 8) * 48 + j * 8 + 2 * q] = make_float2(c[j][2], c[j][3]);
            }
        }
        __syncthreads();

        // reduce + GRU pointwise for the 2 cells owned by this thread
        float hv0, hv1;
        {
            int o = lr0 * 48;
            float gr = sRed[o + uc]      + sRed[768 + o + uc]      + sRed[1536 + o + uc]      + sRed[2304 + o + uc];
            float gz = sRed[o + 16 + uc] + sRed[768 + o + 16 + uc] + sRed[1536 + o + 16 + uc] + sRed[2304 + o + 16 + uc];
            float gn = sRed[o + 32 + uc] + sRed[768 + o + 32 + uc] + sRed[1536 + o + 32 + uc] + sRed[2304 + o + 32 + uc];
            float rr = sigf(xr0 + gr + sBhh[uc]);
            float zz = sigf(xz0 + gz + sBhh[16 + uc]);
            float nn = tanhf(xn0 + rr * (gn + sBhh[32 + uc]));
            hv0 = (1.0f - zz) * nn + zz * hp0;
        }
        {
            int o = lr1 * 48;
            float gr = sRed[o + uc]      + sRed[768 + o + uc]      + sRed[1536 + o + uc]      + sRed[2304 + o + uc];
            float gz = sRed[o + 16 + uc] + sRed[768 + o + 16 + uc] + sRed[1536 + o + 16 + uc] + sRed[2304 + o + 16 + uc];
            float gn = sRed[o + 32 + uc] + sRed[768 + o + 32 + uc] + sRed[1536 + o + 32 + uc] + sRed[2304 + o + 32 + uc];
            float rr = sigf(xr1 + gr + sBhh[uc]);
            float zz = sigf(xz1 + gz + sBhh[16 + uc]);
            float nn = tanhf(xn1 + rr * (gn + sBhh[32 + uc]));
            hv1 = (1.0f - zz) * nn + zz * hp1;
        }
        // publish next-h slice (must precede release)
        buf[(1 - par) * 4096 + lr0 * 256 + gu] = hv0;
        buf[(1 - par) * 4096 + lr1 * 256 + gu] = hv1;
        __syncthreads();                    // all buf writes ordered before release
        if (tid == 0) red_rel(cnt, 1u);

        // overlap with the barrier wait: xi prefetch for t+1 + streaming outputs
        if (t + 1 < 1024) {
            int tt = dir ? (1023 - (t + 1)) : (t + 1);
            const float* x0 = xi + ((size_t)(bs * 16 + lr0) * 1024 + tt) * 768;
            const float* x1 = xi + ((size_t)(bs * 16 + lr1) * 1024 + tt) * 768;
            xr0 = x0[gu]; xz0 = x0[256 + gu]; xn0 = x0[512 + gu];
            xr1 = x1[gu]; xz1 = x1[256 + gu]; xn1 = x1[512 + gu];
        }
        outp[row0 * 256 + gu] = hv0;
        outp[row1 * 256 + gu] = hv1;

        target += 16u;
        if (tid == 0) { while (ld_acq(cnt) < target) {} }
        __syncthreads();
    }
}

// ---------------- pooling: partial mean over S (4 chunks), both encodes ----------------
__global__ void pool_kernel() {
    int b = blockIdx.x, cch = blockIdx.y, d = threadIdx.x;
    const float* h0 = g_hn + ((size_t)b * 1024 + cch * 256) * 256 + d;
    const float* h1 = g_hn + ((size_t)(32 + b) * 1024 + cch * 256) * 256 + d;
    float s = 0.f;
#pragma unroll 4
    for (int si = 0; si < 256; si++) s += h0[(size_t)si * 256] + h1[(size_t)si * 256];
    g_pool[((size_t)cch * 32 + b) * 256 + d] = s;
}

// ---------------- head: proj to O=64, LN, exact GELU ----------------
__global__ void head_kernel(const float* __restrict__ pw, const float* __restrict__ pb,
                            const float* __restrict__ pg, const float* __restrict__ pbt,
                            float* __restrict__ out) {
    __shared__ float pooled[256];
    __shared__ float sp[64];
    int b = blockIdx.x, o = threadIdx.x;   // 64 threads
    for (int k = o; k < 256; k += 64) {
        float s = 0.f;
#pragma unroll
        for (int cch = 0; cch < 4; cch++) s += g_pool[((size_t)cch * 32 + b) * 256 + k];
        pooled[k] = s * (0.5f / 1024.0f);
    }
    __syncthreads();
    float acc = pb[o];
    for (int k = 0; k < 256; k++) acc += pooled[k] * pw[o * 256 + k];
    sp[o] = acc;
    __syncthreads();
    float m = 0.f;
    for (int k = 0; k < 64; k++) m += sp[k];
    m *= (1.0f / 64.0f);
    float v = 0.f;
    for (int k = 0; k < 64; k++) { float d = sp[k] - m; v += d * d; }
    v *= (1.0f / 64.0f);
    float y = (acc - m) * rsqrtf(v + 1e-5f) * pg[o] + pbt[o];
    out[b * 64 + o] = y * 0.5f * (1.0f + erff(y * 0.70710678118654752f));
}

// ---------------- launch ----------------
extern "C" void kernel_launch(void* const* d_in, const int* in_sizes, int n_in,
                              void* d_out, int out_size) {
    const int*   tok  = (const int*)  d_in[0];
    const float* emb  = (const float*)d_in[1];
    const float* pos  = (const float*)d_in[2];
    const float* lng  = (const float*)d_in[3];
    const float* lnb  = (const float*)d_in[4];
    const float* wihF = (const float*)d_in[5];
    const float* whhF = (const float*)d_in[6];
    const float* bihF = (const float*)d_in[7];
    const float* bhhF = (const float*)d_in[8];
    const float* wihR = (const float*)d_in[9];
    const float* whhR = (const float*)d_in[10];
    const float* bihR = (const float*)d_in[11];
    const float* bhhR = (const float*)d_in[12];
    const float* wg   = (const float*)d_in[13];
    const float* bg   = (const float*)d_in[14];
    const float* wo   = (const float*)d_in[15];
    const float* bo   = (const float*)d_in[16];
    const float* fng  = (const float*)d_in[17];
    const float* fnb  = (const float*)d_in[18];
    const float* pw   = (const float*)d_in[19];
    const float* pb   = (const float*)d_in[20];
    const float* plg  = (const float*)d_in[21];
    const float* plb  = (const float*)d_in[22];

    float* hf; float* hr; float* xif; float* xir; float* hnp; float* hp; void* cntp;
    cudaGetSymbolAddress((void**)&hf,  g_f);
    cudaGetSymbolAddress((void**)&hr,  g_r);
    cudaGetSymbolAddress((void**)&xif, g_xif);
    cudaGetSymbolAddress((void**)&xir, g_xir);
    cudaGetSymbolAddress((void**)&hnp, g_hn);
    cudaGetSymbolAddress((void**)&hp,  g_h);
    cudaGetSymbolAddress(&cntp, g_cnt);

    cudaFuncSetAttribute(rnn_kernel, cudaFuncAttributeMaxDynamicSharedMemorySize, RNN_SMEM);

    embed_kernel<<<65536, 256>>>(tok, emb, pos);

    for (int i = 0; i < 4; i++) {
        const float* wihFi = wihF + (size_t)i * 768 * 256;
        const float* whhFi = whhF + (size_t)i * 768 * 256;
        const float* bihFi = bihF + (size_t)i * 768;
        const float* bhhFi = bhhF + (size_t)i * 768;
        const float* wihRi = wihR + (size_t)i * 768 * 256;
        const float* whhRi = whhR + (size_t)i * 768 * 256;
        const float* bihRi = bihR + (size_t)i * 768;
        const float* bhhRi = bhhR + (size_t)i * 768;
        const float* wgi   = wg + (size_t)i * 256 * 512;
        const float* bgi   = bg + (size_t)i * 256;
        const float* woi   = wo + (size_t)i * 256 * 256;
        const float* boi   = bo + (size_t)i * 256;

        ln_kernel<<<8192, 256>>>(hp, lng + i * 256, lnb + i * 256, hnp);
        gemm_kernel<0><<<dim3(12, 512), 256>>>(hnp, nullptr, wihFi, bihFi, xif);
        gemm_kernel<0><<<dim3(12, 512), 256>>>(hnp, nullptr, wihRi, bihRi, xir);
        cudaMemsetAsync(cntp, 0, 8 * 64 * sizeof(unsigned));
        rnn_kernel<<<128, 128, RNN_SMEM>>>(whhFi, whhRi, bhhFi, bhhRi);
        gemm_kernel<1><<<dim3(4, 512), 256>>>(hf, hr, wgi, bgi, hnp);     // hn <- gated c
        gemm_kernel<2><<<dim3(4, 512), 256>>>(hnp, nullptr, woi, boi, hp); // h += c@wo^T+bo
    }

    ln_kernel<<<8192, 256>>>(hp, fng, fnb, hnp);
    pool_kernel<<<dim3(32, 4), 256>>>();
    head_kernel<<<32, 64>>>(pw, pb, plg, plb, (float*)d_out);
}